// round 16
// baseline (speedup 1.0000x reference)
#include <cuda_runtime.h>
#include <cuda_bf16.h>

// Problem constants (fixed by the dataset)
#define B 8
#define L 2048
#define H 1024
#define C 64
#define RPB 32                     // rows per block (4 chunks x 8 warps)
#define GRID (B * L / RPB)         // 512 blocks
#define BPB (L / RPB)              // 64 blocks per batch

// Persistent scratch (zero-initialized at module load; self-reset each launch)
__device__ float        g_acc[B * C];
__device__ unsigned int g_count;

// ---------------------------------------------------------------------------
// FINAL (reproduced 3x at 10.72-10.75us = warm-L2 LTS ceiling):
//   - chunk-0 prefetch: 4 LDG.128/lane issued BEFORE the weight barrier
//   - weight staging: single LDG.128 + STS.128 per thread (H/4 == blockDim)
//   - barrier-free 4-chunk warp-per-row streaming body
//   - fence-free value-returning-atomic scatter (release via consumed ATOMG
//     return, no MEMBAR/CCTL.IVALL) + last-block finalize
// ---------------------------------------------------------------------------
__global__ __launch_bounds__(256) void fused_kernel(
    const float* __restrict__ feature,       // [B*L, H]
    const float* __restrict__ fc_weight,     // [H]
    const float* __restrict__ fc_bias,       // [1]
    const int*   __restrict__ position_list, // [B*C*2]
    float* __restrict__ out)                 // [B*C]
{
    __shared__ float4 sw4[H / 4];            // weights (4 KB), float4-staged
    __shared__ float  sproj[RPB];
    __shared__ bool   is_last;
    __shared__ int    s_sink;                // forces atomic-return consumption

    const int tid   = threadIdx.x;
    const int blk   = blockIdx.x;
    const int batch = blk / BPB;
    const int row0  = (blk % BPB) * RPB;
    const int warp  = tid >> 5;
    const int lane  = tid & 31;

    // Chunk-0 prefetch: 4 independent LDG.128/lane before the barrier.
    const float4* __restrict__ f4_0 = reinterpret_cast<const float4*>(
        feature + (size_t)(batch * L + row0 + warp) * H);
    float4 p0 = f4_0[0 * 32 + lane];
    float4 p1 = f4_0[1 * 32 + lane];
    float4 p2 = f4_0[2 * 32 + lane];
    float4 p3 = f4_0[3 * 32 + lane];

    // Weight staging: exactly one float4 per thread (256 * 16B = 4 KB)
    sw4[tid] = reinterpret_cast<const float4*>(fc_weight)[tid];
    __syncthreads();

    const float4* __restrict__ w4 = sw4;

    // --- Stage 1: 4 chunks of 8 rows, warp-per-row ---
    #pragma unroll
    for (int c = 0; c < 4; c++) {
        const float4* __restrict__ f4 = reinterpret_cast<const float4*>(
            feature + (size_t)(batch * L + row0 + c * 8 + warp) * H);

        float acc = 0.0f;
        if (c == 0) {
            {
                float4 w = w4[0 * 32 + lane];
                acc = fmaf(p0.x, w.x, acc); acc = fmaf(p0.y, w.y, acc);
                acc = fmaf(p0.z, w.z, acc); acc = fmaf(p0.w, w.w, acc);
            }
            {
                float4 w = w4[1 * 32 + lane];
                acc = fmaf(p1.x, w.x, acc); acc = fmaf(p1.y, w.y, acc);
                acc = fmaf(p1.z, w.z, acc); acc = fmaf(p1.w, w.w, acc);
            }
            {
                float4 w = w4[2 * 32 + lane];
                acc = fmaf(p2.x, w.x, acc); acc = fmaf(p2.y, w.y, acc);
                acc = fmaf(p2.z, w.z, acc); acc = fmaf(p2.w, w.w, acc);
            }
            {
                float4 w = w4[3 * 32 + lane];
                acc = fmaf(p3.x, w.x, acc); acc = fmaf(p3.y, w.y, acc);
                acc = fmaf(p3.z, w.z, acc); acc = fmaf(p3.w, w.w, acc);
            }
            #pragma unroll
            for (int i = 4; i < 8; i++) {
                const int idx = i * 32 + lane;
                float4 v = f4[idx];
                float4 w = w4[idx];
                acc = fmaf(v.x, w.x, acc); acc = fmaf(v.y, w.y, acc);
                acc = fmaf(v.z, w.z, acc); acc = fmaf(v.w, w.w, acc);
            }
        } else {
            #pragma unroll
            for (int i = 0; i < 8; i++) {
                const int idx = i * 32 + lane;
                float4 v = f4[idx];
                float4 w = w4[idx];
                acc = fmaf(v.x, w.x, acc); acc = fmaf(v.y, w.y, acc);
                acc = fmaf(v.z, w.z, acc); acc = fmaf(v.w, w.w, acc);
            }
        }
        #pragma unroll
        for (int o = 16; o > 0; o >>= 1)
            acc += __shfl_xor_sync(0xFFFFFFFFu, acc, o);
        if (lane == 0) sproj[c * 8 + warp] = acc;
    }
    __syncthreads();

    // --- Stage 2: scatter into span accumulators (threads 0..63) ---
    if (tid < C) {
        const int si  = (batch * C + tid) * 2;   // L2-hot global read
        const int src = position_list[si + 0];
        const int end = position_list[si + 1];
        int lo = src - row0; if (lo < 0) lo = 0;
        int hi = end - row0; if (hi > RPB - 1) hi = RPB - 1;
        if (lo <= hi) {
            float s = 0.0f;
            #pragma unroll
            for (int r = 0; r < RPB; r++)
                if (r >= lo && r <= hi) s += sproj[r];
            // Value-returning atomic: L2 completion observed before the
            // (never-true) predicate -> release ordering for the g_count
            // arrival without MEMBAR/CCTL.IVALL.
            float old = atomicAdd(&g_acc[batch * C + tid], s);
            if (__float_as_uint(old) == 0xDEADBEEFu) s_sink = 1;
        }
    }
    __syncthreads();   // all scatter atomics of this block have completed

    // --- Stage 3: arrive; last block finalizes ---
    if (tid == 0) {
        unsigned int prev = atomicAdd(&g_count, 1u);
        is_last = (prev == GRID - 1);
    }
    __syncthreads();

    if (is_last) {
        const float bias = fc_bias[0];
        #pragma unroll
        for (int k = 0; k < 2; k++) {
            const int i = tid + k * 256;     // 0..511
            const int src = position_list[i * 2 + 0];
            const int end = position_list[i * 2 + 1];
            const float v = __ldcg(&g_acc[i]);        // L2-coherent read
            out[i] = v / (float)(end - src + 1) + bias;
            __stcg(&g_acc[i], 0.0f);                  // reset for next launch
        }
        if (tid == 0) g_count = 0u;
    }
}

// ---------------------------------------------------------------------------
extern "C" void kernel_launch(void* const* d_in, const int* in_sizes, int n_in,
                              void* d_out, int out_size) {
    const float* feature       = (const float*)d_in[0];  // [B,L,H] f32
    const float* fc_weight     = (const float*)d_in[1];  // [1,H]   f32
    const float* fc_bias       = (const float*)d_in[2];  // [1]     f32
    const int*   position_list = (const int*)  d_in[3];  // [B,C,2] i32
    float* out = (float*)d_out;                          // [B*C,1] f32

    fused_kernel<<<GRID, 256>>>(feature, fc_weight, fc_bias,
                                position_list, out);
}

// round 17
// speedup vs baseline: 1.0238x; 1.0238x over previous
#include <cuda_runtime.h>
#include <cuda_bf16.h>

// Problem constants (fixed by the dataset)
#define B 8
#define L 2048
#define H 1024
#define C 64
#define RPB 32                     // rows per block (4 chunks x 8 warps)
#define GRID (B * L / RPB)         // 512 blocks
#define BPB (L / RPB)              // 64 blocks per batch

// Persistent scratch (zero-initialized at module load; self-reset each launch)
__device__ float        g_acc[B * C];
__device__ unsigned int g_count;

// ---------------------------------------------------------------------------
// FINAL (reproduced 4x at 10.72-11.01us = warm-L2 LTS ceiling, ~6.3 TB/s):
//   - chunk-0 prefetch: 4 LDG.128/lane issued BEFORE the weight barrier
//   - weight staging: single LDG.128 + STS.128 per thread (H/4 == blockDim)
//   - barrier-free 4-chunk warp-per-row streaming body
//   - fence-free value-returning-atomic scatter (release via consumed ATOMG
//     return, no MEMBAR/CCTL.IVALL) + last-block finalize
// ---------------------------------------------------------------------------
__global__ __launch_bounds__(256) void fused_kernel(
    const float* __restrict__ feature,       // [B*L, H]
    const float* __restrict__ fc_weight,     // [H]
    const float* __restrict__ fc_bias,       // [1]
    const int*   __restrict__ position_list, // [B*C*2]
    float* __restrict__ out)                 // [B*C]
{
    __shared__ float4 sw4[H / 4];            // weights (4 KB), float4-staged
    __shared__ float  sproj[RPB];
    __shared__ bool   is_last;
    __shared__ int    s_sink;                // forces atomic-return consumption

    const int tid   = threadIdx.x;
    const int blk   = blockIdx.x;
    const int batch = blk / BPB;
    const int row0  = (blk % BPB) * RPB;
    const int warp  = tid >> 5;
    const int lane  = tid & 31;

    // Chunk-0 prefetch: 4 independent LDG.128/lane before the barrier.
    const float4* __restrict__ f4_0 = reinterpret_cast<const float4*>(
        feature + (size_t)(batch * L + row0 + warp) * H);
    float4 p0 = f4_0[0 * 32 + lane];
    float4 p1 = f4_0[1 * 32 + lane];
    float4 p2 = f4_0[2 * 32 + lane];
    float4 p3 = f4_0[3 * 32 + lane];

    // Weight staging: exactly one float4 per thread (256 * 16B = 4 KB)
    sw4[tid] = reinterpret_cast<const float4*>(fc_weight)[tid];
    __syncthreads();

    const float4* __restrict__ w4 = sw4;

    // --- Stage 1: 4 chunks of 8 rows, warp-per-row ---
    #pragma unroll
    for (int c = 0; c < 4; c++) {
        const float4* __restrict__ f4 = reinterpret_cast<const float4*>(
            feature + (size_t)(batch * L + row0 + c * 8 + warp) * H);

        float acc = 0.0f;
        if (c == 0) {
            {
                float4 w = w4[0 * 32 + lane];
                acc = fmaf(p0.x, w.x, acc); acc = fmaf(p0.y, w.y, acc);
                acc = fmaf(p0.z, w.z, acc); acc = fmaf(p0.w, w.w, acc);
            }
            {
                float4 w = w4[1 * 32 + lane];
                acc = fmaf(p1.x, w.x, acc); acc = fmaf(p1.y, w.y, acc);
                acc = fmaf(p1.z, w.z, acc); acc = fmaf(p1.w, w.w, acc);
            }
            {
                float4 w = w4[2 * 32 + lane];
                acc = fmaf(p2.x, w.x, acc); acc = fmaf(p2.y, w.y, acc);
                acc = fmaf(p2.z, w.z, acc); acc = fmaf(p2.w, w.w, acc);
            }
            {
                float4 w = w4[3 * 32 + lane];
                acc = fmaf(p3.x, w.x, acc); acc = fmaf(p3.y, w.y, acc);
                acc = fmaf(p3.z, w.z, acc); acc = fmaf(p3.w, w.w, acc);
            }
            #pragma unroll
            for (int i = 4; i < 8; i++) {
                const int idx = i * 32 + lane;
                float4 v = f4[idx];
                float4 w = w4[idx];
                acc = fmaf(v.x, w.x, acc); acc = fmaf(v.y, w.y, acc);
                acc = fmaf(v.z, w.z, acc); acc = fmaf(v.w, w.w, acc);
            }
        } else {
            #pragma unroll
            for (int i = 0; i < 8; i++) {
                const int idx = i * 32 + lane;
                float4 v = f4[idx];
                float4 w = w4[idx];
                acc = fmaf(v.x, w.x, acc); acc = fmaf(v.y, w.y, acc);
                acc = fmaf(v.z, w.z, acc); acc = fmaf(v.w, w.w, acc);
            }
        }
        #pragma unroll
        for (int o = 16; o > 0; o >>= 1)
            acc += __shfl_xor_sync(0xFFFFFFFFu, acc, o);
        if (lane == 0) sproj[c * 8 + warp] = acc;
    }
    __syncthreads();

    // --- Stage 2: scatter into span accumulators (threads 0..63) ---
    if (tid < C) {
        const int si  = (batch * C + tid) * 2;   // L2-hot global read
        const int src = position_list[si + 0];
        const int end = position_list[si + 1];
        int lo = src - row0; if (lo < 0) lo = 0;
        int hi = end - row0; if (hi > RPB - 1) hi = RPB - 1;
        if (lo <= hi) {
            float s = 0.0f;
            #pragma unroll
            for (int r = 0; r < RPB; r++)
                if (r >= lo && r <= hi) s += sproj[r];
            // Value-returning atomic: L2 completion observed before the
            // (never-true) predicate -> release ordering for the g_count
            // arrival without MEMBAR/CCTL.IVALL.
            float old = atomicAdd(&g_acc[batch * C + tid], s);
            if (__float_as_uint(old) == 0xDEADBEEFu) s_sink = 1;
        }
    }
    __syncthreads();   // all scatter atomics of this block have completed

    // --- Stage 3: arrive; last block finalizes ---
    if (tid == 0) {
        unsigned int prev = atomicAdd(&g_count, 1u);
        is_last = (prev == GRID - 1);
    }
    __syncthreads();

    if (is_last) {
        const float bias = fc_bias[0];
        #pragma unroll
        for (int k = 0; k < 2; k++) {
            const int i = tid + k * 256;     // 0..511
            const int src = position_list[i * 2 + 0];
            const int end = position_list[i * 2 + 1];
            const float v = __ldcg(&g_acc[i]);        // L2-coherent read
            out[i] = v / (float)(end - src + 1) + bias;
            __stcg(&g_acc[i], 0.0f);                  // reset for next launch
        }
        if (tid == 0) g_count = 0u;
    }
}

// ---------------------------------------------------------------------------
extern "C" void kernel_launch(void* const* d_in, const int* in_sizes, int n_in,
                              void* d_out, int out_size) {
    const float* feature       = (const float*)d_in[0];  // [B,L,H] f32
    const float* fc_weight     = (const float*)d_in[1];  // [1,H]   f32
    const float* fc_bias       = (const float*)d_in[2];  // [1]     f32
    const int*   position_list = (const int*)  d_in[3];  // [B,C,2] i32
    float* out = (float*)d_out;                          // [B*C,1] f32

    fused_kernel<<<GRID, 256>>>(feature, fc_weight, fc_bias,
                                position_list, out);
}